// round 1
// baseline (speedup 1.0000x reference)
#include <cuda_runtime.h>

// ---------------------------------------------------------------------------
// net: conv3x3(3->10)+relu -> conv3x3(10->20)+relu -> FC(2880->500) ->
//      heaviside(>=0 -> 1 else 0) -> FC(500->10)
// B = 65536, x [B,3,16,16]
// ---------------------------------------------------------------------------

#define B_TOTAL 65536

// scratch (static device globals; no allocation allowed)
__device__ float g_h2[(size_t)B_TOTAL * 2880];         // conv2 output, flattened NCHW
__device__ unsigned char g_s[(size_t)B_TOTAL * 500];   // heaviside sign bytes

// ---------------------------------------------------------------------------
// Kernel 1: fused conv1+relu+conv2+relu, one sample per block.
// ---------------------------------------------------------------------------
__global__ __launch_bounds__(256)
void conv_fused_kernel(const float* __restrict__ x,
                       const float* __restrict__ w1, const float* __restrict__ b1,
                       const float* __restrict__ w2, const float* __restrict__ b2)
{
    __shared__ float sx[768];     // [3][16][16]
    __shared__ float sw1[270];    // [10][3][3][3]
    __shared__ float sw2[1800];   // [20][10][3][3]
    __shared__ float sh1[1960];   // [10][14][14]

    const int b = blockIdx.x;
    const int tid = threadIdx.x;

    const float* xb = x + (size_t)b * 768;
    for (int i = tid; i < 768; i += 256)  sx[i]  = xb[i];
    for (int i = tid; i < 270; i += 256)  sw1[i] = w1[i];
    for (int i = tid; i < 1800; i += 256) sw2[i] = w2[i];
    __syncthreads();

    // conv1: 140 row-tasks (oc in [0,10), oy in [0,14)), each computes 14 outputs
    if (tid < 140) {
        const int oc = tid / 14;
        const int oy = tid % 14;
        float acc[14];
        const float bias = b1[oc];
        #pragma unroll
        for (int i = 0; i < 14; i++) acc[i] = bias;

        #pragma unroll
        for (int ic = 0; ic < 3; ic++) {
            const float* xr = sx + ic * 256 + oy * 16;
            const float* w  = sw1 + oc * 27 + ic * 9;
            #pragma unroll
            for (int ky = 0; ky < 3; ky++) {
                const float* row = xr + ky * 16;
                const float wa = w[ky * 3 + 0];
                const float wb = w[ky * 3 + 1];
                const float wc = w[ky * 3 + 2];
                #pragma unroll
                for (int ox = 0; ox < 14; ox++)
                    acc[ox] += wa * row[ox] + wb * row[ox + 1] + wc * row[ox + 2];
            }
        }
        float* out = sh1 + oc * 196 + oy * 14;
        #pragma unroll
        for (int i = 0; i < 14; i++) out[i] = fmaxf(acc[i], 0.f);
    }
    __syncthreads();

    // conv2: 240 row-tasks (oc in [0,20), oy in [0,12)), each computes 12 outputs
    if (tid < 240) {
        const int oc = tid / 12;
        const int oy = tid % 12;
        float acc[12];
        const float bias = b2[oc];
        #pragma unroll
        for (int i = 0; i < 12; i++) acc[i] = bias;

        for (int ic = 0; ic < 10; ic++) {
            const float* hr = sh1 + ic * 196 + oy * 14;
            const float* w  = sw2 + oc * 90 + ic * 9;
            #pragma unroll
            for (int ky = 0; ky < 3; ky++) {
                const float* row = hr + ky * 14;
                const float wa = w[ky * 3 + 0];
                const float wb = w[ky * 3 + 1];
                const float wc = w[ky * 3 + 2];
                #pragma unroll
                for (int ox = 0; ox < 12; ox++)
                    acc[ox] += wa * row[ox] + wb * row[ox + 1] + wc * row[ox + 2];
            }
        }
        // flatten index: oc*144 + oy*12 + ox  (NCHW flatten, matches reshape)
        float4 v0, v1, v2;
        v0.x = fmaxf(acc[0], 0.f);  v0.y = fmaxf(acc[1], 0.f);
        v0.z = fmaxf(acc[2], 0.f);  v0.w = fmaxf(acc[3], 0.f);
        v1.x = fmaxf(acc[4], 0.f);  v1.y = fmaxf(acc[5], 0.f);
        v1.z = fmaxf(acc[6], 0.f);  v1.w = fmaxf(acc[7], 0.f);
        v2.x = fmaxf(acc[8], 0.f);  v2.y = fmaxf(acc[9], 0.f);
        v2.z = fmaxf(acc[10], 0.f); v2.w = fmaxf(acc[11], 0.f);
        float* out = g_h2 + (size_t)b * 2880 + oc * 144 + oy * 12;
        reinterpret_cast<float4*>(out)[0] = v0;
        reinterpret_cast<float4*>(out)[1] = v1;
        reinterpret_cast<float4*>(out)[2] = v2;
    }
}

// ---------------------------------------------------------------------------
// Kernel 2: FC1 GEMM  C[B,500] = H[B,2880] @ W^T + b, then heaviside -> bytes.
// 128x128 block tile, BK=16, 256 threads, 8x8 register tile per thread.
// ---------------------------------------------------------------------------
__global__ __launch_bounds__(256)
void fc1_kernel(const float* __restrict__ W, const float* __restrict__ bias)
{
    __shared__ float As[16][132];   // [k][m], padded
    __shared__ float Bs[16][132];   // [k][n], padded

    const int tid = threadIdx.x;
    const int n0 = blockIdx.x * 128;
    const int m0 = blockIdx.y * 128;
    const int ty = tid >> 4;    // 0..15
    const int tx = tid & 15;    // 0..15

    float acc[8][8];
    #pragma unroll
    for (int i = 0; i < 8; i++)
        #pragma unroll
        for (int j = 0; j < 8; j++) acc[i][j] = 0.f;

    for (int k0 = 0; k0 < 2880; k0 += 16) {
        // load A tile: 128 rows x 16 k  (512 float4, 2 per thread)
        #pragma unroll
        for (int i = 0; i < 2; i++) {
            const int idx = i * 256 + tid;
            const int m   = idx >> 2;
            const int kq  = (idx & 3) * 4;
            const float4 v = *reinterpret_cast<const float4*>(
                g_h2 + (size_t)(m0 + m) * 2880 + k0 + kq);
            As[kq + 0][m] = v.x; As[kq + 1][m] = v.y;
            As[kq + 2][m] = v.z; As[kq + 3][m] = v.w;
        }
        // load B tile: 128 n x 16 k, zero-fill beyond n=500
        #pragma unroll
        for (int i = 0; i < 2; i++) {
            const int idx = i * 256 + tid;
            const int n   = idx >> 2;
            const int kq  = (idx & 3) * 4;
            float4 v = make_float4(0.f, 0.f, 0.f, 0.f);
            if (n0 + n < 500)
                v = *reinterpret_cast<const float4*>(
                    W + (size_t)(n0 + n) * 2880 + k0 + kq);
            Bs[kq + 0][n] = v.x; Bs[kq + 1][n] = v.y;
            Bs[kq + 2][n] = v.z; Bs[kq + 3][n] = v.w;
        }
        __syncthreads();

        #pragma unroll
        for (int k = 0; k < 16; k++) {
            float a[8], bb[8];
            *reinterpret_cast<float4*>(a)      = *reinterpret_cast<const float4*>(&As[k][ty * 8]);
            *reinterpret_cast<float4*>(a + 4)  = *reinterpret_cast<const float4*>(&As[k][ty * 8 + 4]);
            *reinterpret_cast<float4*>(bb)     = *reinterpret_cast<const float4*>(&Bs[k][tx * 8]);
            *reinterpret_cast<float4*>(bb + 4) = *reinterpret_cast<const float4*>(&Bs[k][tx * 8 + 4]);
            #pragma unroll
            for (int i = 0; i < 8; i++)
                #pragma unroll
                for (int j = 0; j < 8; j++)
                    acc[i][j] += a[i] * bb[j];
        }
        __syncthreads();
    }

    // epilogue: +bias, heaviside, pack sign bytes
    const int nbase = n0 + tx * 8;
    float bb[8];
    #pragma unroll
    for (int j = 0; j < 8; j++)
        bb[j] = (nbase + j < 500) ? bias[nbase + j] : 0.f;

    #pragma unroll
    for (int i = 0; i < 8; i++) {
        const int m = m0 + ty * 8 + i;
        unsigned int u0 = 0, u1 = 0;
        #pragma unroll
        for (int j = 0; j < 4; j++)
            u0 |= ((acc[i][j] + bb[j] >= 0.f) ? 1u : 0u) << (8 * j);
        #pragma unroll
        for (int j = 0; j < 4; j++)
            u1 |= ((acc[i][4 + j] + bb[4 + j] >= 0.f) ? 1u : 0u) << (8 * j);
        const size_t base = (size_t)m * 500 + nbase;
        if (nbase + 8 <= 500) {
            *reinterpret_cast<unsigned int*>(g_s + base)     = u0;
            *reinterpret_cast<unsigned int*>(g_s + base + 4) = u1;
        } else if (nbase + 4 <= 500) {   // n = 496..499 remainder
            *reinterpret_cast<unsigned int*>(g_s + base) = u0;
        }
    }
}

// ---------------------------------------------------------------------------
// Kernel 3: FC2 on binary signs: out[b,i] = sum_j s[b,j]*W2[i,j] + b2[i]
// ---------------------------------------------------------------------------
__global__ __launch_bounds__(256)
void fc2_kernel(const float* __restrict__ W2, const float* __restrict__ b2,
                float* __restrict__ out)
{
    __shared__ float sw[5000];   // [10][500]
    const int tid = threadIdx.x;
    for (int i = tid; i < 5000; i += 256) sw[i] = W2[i];
    __syncthreads();

    const size_t b = (size_t)blockIdx.x * 256 + tid;
    const unsigned char* srow = g_s + b * 500;

    float acc[10];
    #pragma unroll
    for (int i = 0; i < 10; i++) acc[i] = b2[i];

    for (int j = 0; j < 500; j += 4) {
        const uchar4 s4 = *reinterpret_cast<const uchar4*>(srow + j);
        const float s0 = (float)s4.x, s1 = (float)s4.y;
        const float s2 = (float)s4.z, s3 = (float)s4.w;
        #pragma unroll
        for (int i = 0; i < 10; i++) {
            const float* w = sw + i * 500 + j;
            acc[i] += s0 * w[0] + s1 * w[1] + s2 * w[2] + s3 * w[3];
        }
    }
    float* o = out + b * 10;
    #pragma unroll
    for (int i = 0; i < 10; i++) o[i] = acc[i];
}

// ---------------------------------------------------------------------------
extern "C" void kernel_launch(void* const* d_in, const int* in_sizes, int n_in,
                              void* d_out, int out_size)
{
    const float* x    = (const float*)d_in[0];
    const float* w1   = (const float*)d_in[1];
    const float* b1   = (const float*)d_in[2];
    const float* w2   = (const float*)d_in[3];
    const float* b2   = (const float*)d_in[4];
    const float* fcw  = (const float*)d_in[5];
    const float* fcb  = (const float*)d_in[6];
    const float* fc2w = (const float*)d_in[7];
    const float* fc2b = (const float*)d_in[8];

    conv_fused_kernel<<<B_TOTAL, 256>>>(x, w1, b1, w2, b2);

    dim3 g1(4, 512);                       // N tiles x M tiles
    fc1_kernel<<<g1, 256>>>(fcw, fcb);

    fc2_kernel<<<B_TOTAL / 256, 256>>>(fc2w, fc2b, (float*)d_out);
}

// round 3
// speedup vs baseline: 1.3986x; 1.3986x over previous
#include <cuda_runtime.h>
#include <cuda_bf16.h>
#include <cstdint>

// ---------------------------------------------------------------------------
// net: conv3x3(3->10)+relu -> conv3x3(10->20)+relu -> FC(2880->500) ->
//      heaviside(>=0 -> 1 else 0) -> FC(500->10)
// B = 65536
//
// FC1 on tensor cores (mma.sync bf16, baseline PTX — no sm_103a features),
// 2-way bf16 split x 3 products, fp32 accumulate. Near-zero outputs
// (|v| < 1e-4) recomputed in fp64 since only the SIGN survives Heaviside.
// ---------------------------------------------------------------------------

#define B_TOTAL 65536
#define KDIM 2880
#define NOUT 500
#define NPAD 512
#define FIX_CAP (1u*1024u*1024u)
#define T_FIX 1e-4f

__device__ float          g_h2[(size_t)B_TOTAL * KDIM];   // fp32 activations
__device__ __nv_bfloat16  g_a0[(size_t)B_TOTAL * KDIM];   // bf16 hi split
__device__ __nv_bfloat16  g_a1[(size_t)B_TOTAL * KDIM];   // bf16 lo split
__device__ __nv_bfloat16  g_b0[(size_t)NPAD * KDIM];      // weight hi split
__device__ __nv_bfloat16  g_b1[(size_t)NPAD * KDIM];      // weight lo split
__device__ unsigned char  g_s[(size_t)B_TOTAL * NOUT];    // heaviside bytes
__device__ unsigned int   g_fix[FIX_CAP];                 // fixup worklist
__device__ unsigned int   g_nfix;

__device__ __forceinline__ uint32_t smem_u32(const void* p) {
    uint32_t a;
    asm("{ .reg .u64 t; cvta.to.shared.u64 t, %1; cvt.u32.u64 %0, t; }" : "=r"(a) : "l"(p));
    return a;
}

__device__ __forceinline__ void cp16(uint32_t dst, const void* src) {
    asm volatile("cp.async.cg.shared.global [%0], [%1], 16;" :: "r"(dst), "l"(src));
}

__device__ __forceinline__ void ldx4(uint32_t* r, uint32_t addr) {
    asm volatile("ldmatrix.sync.aligned.m8n8.x4.shared.b16 {%0,%1,%2,%3}, [%4];"
                 : "=r"(r[0]), "=r"(r[1]), "=r"(r[2]), "=r"(r[3]) : "r"(addr));
}

__device__ __forceinline__ void mma16816(float* c, const uint32_t* a,
                                         uint32_t b0, uint32_t b1) {
    asm volatile(
        "mma.sync.aligned.m16n8k16.row.col.f32.bf16.bf16.f32 "
        "{%0,%1,%2,%3}, {%4,%5,%6,%7}, {%8,%9}, {%0,%1,%2,%3};"
        : "+f"(c[0]), "+f"(c[1]), "+f"(c[2]), "+f"(c[3])
        : "r"(a[0]), "r"(a[1]), "r"(a[2]), "r"(a[3]), "r"(b0), "r"(b1));
}

// ---------------------------------------------------------------------------
// Kernel 0: weight split prep + counter reset
// ---------------------------------------------------------------------------
__global__ __launch_bounds__(256)
void prep_kernel(const float* __restrict__ W)
{
    const size_t idx = (size_t)blockIdx.x * 256 + threadIdx.x;
    if (idx == 0) g_nfix = 0;
    if (idx >= (size_t)NPAD * KDIM) return;
    const int n = (int)(idx / KDIM);
    const float w = (n < NOUT) ? W[(size_t)n * KDIM + (idx % KDIM)] : 0.f;
    const __nv_bfloat16 hi = __float2bfloat16(w);
    g_b0[idx] = hi;
    g_b1[idx] = __float2bfloat16(w - __bfloat162float(hi));
}

// ---------------------------------------------------------------------------
// Kernel 1: fused conv1+relu+conv2+relu; writes fp32 h2 + bf16 splits
// ---------------------------------------------------------------------------
__global__ __launch_bounds__(256)
void conv_fused_kernel(const float* __restrict__ x,
                       const float* __restrict__ w1, const float* __restrict__ b1,
                       const float* __restrict__ w2, const float* __restrict__ b2)
{
    __shared__ float sx[768];
    __shared__ float sw1[270];
    __shared__ float sw2[1800];
    __shared__ float sh1[1960];

    const int b = blockIdx.x;
    const int tid = threadIdx.x;

    const float* xb = x + (size_t)b * 768;
    for (int i = tid; i < 768; i += 256)  sx[i]  = xb[i];
    for (int i = tid; i < 270; i += 256)  sw1[i] = w1[i];
    for (int i = tid; i < 1800; i += 256) sw2[i] = w2[i];
    __syncthreads();

    if (tid < 140) {
        const int oc = tid / 14;
        const int oy = tid % 14;
        float acc[14];
        const float bias = b1[oc];
        #pragma unroll
        for (int i = 0; i < 14; i++) acc[i] = bias;

        #pragma unroll
        for (int ic = 0; ic < 3; ic++) {
            const float* xr = sx + ic * 256 + oy * 16;
            const float* w  = sw1 + oc * 27 + ic * 9;
            #pragma unroll
            for (int ky = 0; ky < 3; ky++) {
                const float* row = xr + ky * 16;
                const float wa = w[ky * 3 + 0];
                const float wb = w[ky * 3 + 1];
                const float wc = w[ky * 3 + 2];
                #pragma unroll
                for (int ox = 0; ox < 14; ox++)
                    acc[ox] += wa * row[ox] + wb * row[ox + 1] + wc * row[ox + 2];
            }
        }
        float* out = sh1 + oc * 196 + oy * 14;
        #pragma unroll
        for (int i = 0; i < 14; i++) out[i] = fmaxf(acc[i], 0.f);
    }
    __syncthreads();

    if (tid < 240) {
        const int oc = tid / 12;
        const int oy = tid % 12;
        float acc[12];
        const float bias = b2[oc];
        #pragma unroll
        for (int i = 0; i < 12; i++) acc[i] = bias;

        for (int ic = 0; ic < 10; ic++) {
            const float* hr = sh1 + ic * 196 + oy * 14;
            const float* w  = sw2 + oc * 90 + ic * 9;
            #pragma unroll
            for (int ky = 0; ky < 3; ky++) {
                const float* row = hr + ky * 14;
                const float wa = w[ky * 3 + 0];
                const float wb = w[ky * 3 + 1];
                const float wc = w[ky * 3 + 2];
                #pragma unroll
                for (int ox = 0; ox < 12; ox++)
                    acc[ox] += wa * row[ox] + wb * row[ox + 1] + wc * row[ox + 2];
            }
        }
        float v[12];
        #pragma unroll
        for (int i = 0; i < 12; i++) v[i] = fmaxf(acc[i], 0.f);

        const size_t off = (size_t)b * KDIM + oc * 144 + oy * 12;

        float* outf = g_h2 + off;
        #pragma unroll
        for (int q = 0; q < 3; q++)
            reinterpret_cast<float4*>(outf)[q] =
                make_float4(v[q*4], v[q*4+1], v[q*4+2], v[q*4+3]);

        __nv_bfloat162* p0 = reinterpret_cast<__nv_bfloat162*>(g_a0 + off);
        __nv_bfloat162* p1 = reinterpret_cast<__nv_bfloat162*>(g_a1 + off);
        #pragma unroll
        for (int q = 0; q < 6; q++) {
            const __nv_bfloat16 h0a = __float2bfloat16(v[2*q]);
            const __nv_bfloat16 h0b = __float2bfloat16(v[2*q+1]);
            const __nv_bfloat16 l0a = __float2bfloat16(v[2*q]   - __bfloat162float(h0a));
            const __nv_bfloat16 l0b = __float2bfloat16(v[2*q+1] - __bfloat162float(h0b));
            p0[q] = __nv_bfloat162(h0a, h0b);
            p1[q] = __nv_bfloat162(l0a, l0b);
        }
    }
}

// ---------------------------------------------------------------------------
// Kernel 2: FC1 via mma.sync bf16, 128x128 CTA tile, BK=32, 3-stage cp.async.
// smem rows padded to 80B (conflict-free ldmatrix).
// ---------------------------------------------------------------------------
#define BK 32
#define PITCH 80
#define TILE_BYTES (128 * PITCH)      // 10240
#define STAGE_BYTES (4 * TILE_BYTES)  // 40960 : A0,A1,B0,B1
#define NSTAGE 3
#define FC1_SMEM (NSTAGE * STAGE_BYTES)

__device__ __forceinline__ void load_stage(uint32_t sb,
                                           const __nv_bfloat16* ga0,
                                           const __nv_bfloat16* ga1,
                                           const __nv_bfloat16* gb0,
                                           const __nv_bfloat16* gb1,
                                           int k0, int tid)
{
    const __nv_bfloat16* srcs[4] = { ga0 + k0, ga1 + k0, gb0 + k0, gb1 + k0 };
    #pragma unroll
    for (int t = 0; t < 4; ++t) {
        #pragma unroll
        for (int h = 0; h < 2; ++h) {
            const int idx = h * 256 + tid;        // 0..511
            const int r = idx >> 2, c = idx & 3;
            cp16(sb + t * TILE_BYTES + r * PITCH + c * 16,
                 srcs[t] + (size_t)r * KDIM + c * 8);
        }
    }
}

__global__ __launch_bounds__(256, 1)
void fc1_mma_kernel(const float* __restrict__ bias)
{
    extern __shared__ char sm[];
    const uint32_t smb = smem_u32(sm);
    const int tid  = threadIdx.x;
    const int lane = tid & 31;
    const int wid  = tid >> 5;
    const int n0 = blockIdx.x * 128;
    const int m0 = blockIdx.y * 128;

    const int m_off = (wid & 1) * 64;   // warp covers 64 m
    const int n_off = (wid >> 1) * 32;  // warp covers 32 n

    const __nv_bfloat16* ga0 = g_a0 + (size_t)m0 * KDIM;
    const __nv_bfloat16* ga1 = g_a1 + (size_t)m0 * KDIM;
    const __nv_bfloat16* gb0 = g_b0 + (size_t)n0 * KDIM;
    const __nv_bfloat16* gb1 = g_b1 + (size_t)n0 * KDIM;

    float acc[4][4][4];
    #pragma unroll
    for (int i = 0; i < 4; i++)
        #pragma unroll
        for (int j = 0; j < 4; j++)
            #pragma unroll
            for (int q = 0; q < 4; q++) acc[i][j][q] = 0.f;

    // prologue: stages 0,1
    load_stage(smb, ga0, ga1, gb0, gb1, 0, tid);
    asm volatile("cp.async.commit_group;");
    load_stage(smb + STAGE_BYTES, ga0, ga1, gb0, gb1, BK, tid);
    asm volatile("cp.async.commit_group;");

    // per-lane ldmatrix address offsets
    const uint32_t a_lane = (uint32_t)(lane & 15) * PITCH + (uint32_t)(lane >> 4) * 16;
    const uint32_t b_lane = (uint32_t)(lane & 7) * PITCH + (uint32_t)(lane >> 3) * 16;

    for (int i = 0; i < KDIM / BK; ++i) {
        asm volatile("cp.async.wait_group 1;");
        __syncthreads();
        if (i + 2 < KDIM / BK)
            load_stage(smb + ((i + 2) % NSTAGE) * STAGE_BYTES,
                       ga0, ga1, gb0, gb1, (i + 2) * BK, tid);
        asm volatile("cp.async.commit_group;");

        const uint32_t sb = smb + (i % NSTAGE) * STAGE_BYTES;
        const uint32_t A0b = sb;
        const uint32_t A1b = sb + TILE_BYTES;
        const uint32_t B0b = sb + 2 * TILE_BYTES;
        const uint32_t B1b = sb + 3 * TILE_BYTES;

        // B fragments for the whole k32 stage: reg pairs (0,1)=k0-15, (2,3)=k16-31
        uint32_t b0f[4][4], b1f[4][4];
        #pragma unroll
        for (int nt = 0; nt < 4; ++nt) {
            const uint32_t boff = (uint32_t)(n_off + nt * 8) * PITCH + b_lane;
            ldx4(b0f[nt], B0b + boff);
            ldx4(b1f[nt], B1b + boff);
        }

        #pragma unroll
        for (int kk = 0; kk < 2; ++kk) {
            uint32_t a0f[4][4], a1f[4][4];
            #pragma unroll
            for (int mt = 0; mt < 4; ++mt) {
                const uint32_t aoff = (uint32_t)(m_off + mt * 16) * PITCH + a_lane
                                    + (uint32_t)kk * 32;
                ldx4(a0f[mt], A0b + aoff);
                ldx4(a1f[mt], A1b + aoff);
            }
            #pragma unroll
            for (int mt = 0; mt < 4; ++mt)
                #pragma unroll
                for (int nt = 0; nt < 4; ++nt) {
                    mma16816(acc[mt][nt], a0f[mt], b0f[nt][kk*2], b0f[nt][kk*2+1]);
                    mma16816(acc[mt][nt], a0f[mt], b1f[nt][kk*2], b1f[nt][kk*2+1]);
                    mma16816(acc[mt][nt], a1f[mt], b0f[nt][kk*2], b0f[nt][kk*2+1]);
                }
        }
    }

    // epilogue: bias + heaviside -> bytes; flag near-zeros for exact recompute
    const int g  = lane >> 2;
    const int t2 = (lane & 3) * 2;
    #pragma unroll
    for (int mt = 0; mt < 4; ++mt) {
        const int mA = m0 + m_off + mt * 16 + g;
        const int mB = mA + 8;
        #pragma unroll
        for (int nt = 0; nt < 4; ++nt) {
            const int n = n0 + n_off + nt * 8 + t2;
            if (n >= NOUT) continue;
            const float bn0 = __ldg(&bias[n]);
            const float bn1 = __ldg(&bias[n + 1]);

            const float vA0 = acc[mt][nt][0] + bn0;
            const float vA1 = acc[mt][nt][1] + bn1;
            const float vB0 = acc[mt][nt][2] + bn0;
            const float vB1 = acc[mt][nt][3] + bn1;

            unsigned short sA = (vA0 >= 0.f ? 1u : 0u) | ((vA1 >= 0.f ? 1u : 0u) << 8);
            unsigned short sB = (vB0 >= 0.f ? 1u : 0u) | ((vB1 >= 0.f ? 1u : 0u) << 8);
            *reinterpret_cast<unsigned short*>(g_s + (size_t)mA * NOUT + n) = sA;
            *reinterpret_cast<unsigned short*>(g_s + (size_t)mB * NOUT + n) = sB;

            if (fabsf(vA0) < T_FIX || fabsf(vA1) < T_FIX ||
                fabsf(vB0) < T_FIX || fabsf(vB1) < T_FIX) {
                if (fabsf(vA0) < T_FIX) {
                    unsigned int ix = atomicAdd(&g_nfix, 1u);
                    if (ix < FIX_CAP) g_fix[ix] = ((unsigned int)mA << 9) | (unsigned int)n;
                }
                if (fabsf(vA1) < T_FIX) {
                    unsigned int ix = atomicAdd(&g_nfix, 1u);
                    if (ix < FIX_CAP) g_fix[ix] = ((unsigned int)mA << 9) | (unsigned int)(n+1);
                }
                if (fabsf(vB0) < T_FIX) {
                    unsigned int ix = atomicAdd(&g_nfix, 1u);
                    if (ix < FIX_CAP) g_fix[ix] = ((unsigned int)mB << 9) | (unsigned int)n;
                }
                if (fabsf(vB1) < T_FIX) {
                    unsigned int ix = atomicAdd(&g_nfix, 1u);
                    if (ix < FIX_CAP) g_fix[ix] = ((unsigned int)mB << 9) | (unsigned int)(n+1);
                }
            }
        }
    }
}

// ---------------------------------------------------------------------------
// Kernel 3: fp64 recompute of flagged near-zero dots (exact signs)
// ---------------------------------------------------------------------------
__global__ __launch_bounds__(128)
void fixup_kernel(const float* __restrict__ W, const float* __restrict__ bias)
{
    __shared__ double red[128];
    const int tid = threadIdx.x;
    unsigned int total = g_nfix;
    if (total > FIX_CAP) total = FIX_CAP;
    for (unsigned int e = blockIdx.x; e < total; e += gridDim.x) {
        const unsigned int ent = g_fix[e];
        const int m = (int)(ent >> 9);
        const int n = (int)(ent & 511u);
        const float* hr = g_h2 + (size_t)m * KDIM;
        const float* wr = W + (size_t)n * KDIM;
        double part = 0.0;
        for (int k = tid; k < KDIM; k += 128)
            part += (double)hr[k] * (double)wr[k];
        red[tid] = part;
        __syncthreads();
        #pragma unroll
        for (int s = 64; s > 0; s >>= 1) {
            if (tid < s) red[tid] += red[tid + s];
            __syncthreads();
        }
        if (tid == 0) {
            const double v = red[0] + (double)bias[n];
            g_s[(size_t)m * NOUT + n] = (v >= 0.0) ? 1 : 0;
        }
        __syncthreads();
    }
}

// ---------------------------------------------------------------------------
// Kernel 4: FC2 on binary signs
// ---------------------------------------------------------------------------
__global__ __launch_bounds__(256)
void fc2_kernel(const float* __restrict__ W2, const float* __restrict__ b2,
                float* __restrict__ out)
{
    __shared__ float sw[5000];
    const int tid = threadIdx.x;
    for (int i = tid; i < 5000; i += 256) sw[i] = W2[i];
    __syncthreads();

    const size_t b = (size_t)blockIdx.x * 256 + tid;
    const unsigned char* srow = g_s + b * NOUT;

    float acc[10];
    #pragma unroll
    for (int i = 0; i < 10; i++) acc[i] = b2[i];

    for (int j = 0; j < NOUT; j += 4) {
        const uchar4 s4 = *reinterpret_cast<const uchar4*>(srow + j);
        const float s0 = (float)s4.x, s1 = (float)s4.y;
        const float s2 = (float)s4.z, s3 = (float)s4.w;
        #pragma unroll
        for (int i = 0; i < 10; i++) {
            const float* w = sw + i * NOUT + j;
            acc[i] += s0 * w[0] + s1 * w[1] + s2 * w[2] + s3 * w[3];
        }
    }
    float* o = out + b * 10;
    #pragma unroll
    for (int i = 0; i < 10; i++) o[i] = acc[i];
}

// ---------------------------------------------------------------------------
extern "C" void kernel_launch(void* const* d_in, const int* in_sizes, int n_in,
                              void* d_out, int out_size)
{
    const float* x    = (const float*)d_in[0];
    const float* w1   = (const float*)d_in[1];
    const float* b1   = (const float*)d_in[2];
    const float* w2   = (const float*)d_in[3];
    const float* b2   = (const float*)d_in[4];
    const float* fcw  = (const float*)d_in[5];
    const float* fcb  = (const float*)d_in[6];
    const float* fc2w = (const float*)d_in[7];
    const float* fc2b = (const float*)d_in[8];

    cudaFuncSetAttribute(fc1_mma_kernel,
                         cudaFuncAttributeMaxDynamicSharedMemorySize, FC1_SMEM);

    prep_kernel<<<(NPAD * KDIM + 255) / 256, 256>>>(fcw);
    conv_fused_kernel<<<B_TOTAL, 256>>>(x, w1, b1, w2, b2);

    dim3 g1(4, 512);   // 4 N-tiles x 512 M-tiles (consecutive CTAs share m0 -> A L2 reuse)
    fc1_mma_kernel<<<g1, 256, FC1_SMEM>>>(fcb);

    fixup_kernel<<<2048, 128>>>(fcw, fcb);
    fc2_kernel<<<B_TOTAL / 256, 256>>>(fc2w, fc2b, (float*)d_out);
}

// round 4
// speedup vs baseline: 1.6176x; 1.1566x over previous
#include <cuda_runtime.h>
#include <cuda_fp16.h>
#include <cstdint>

// ---------------------------------------------------------------------------
// net: conv3x3(3->10)+relu -> conv3x3(10->20)+relu -> FC(2880->500) ->
//      heaviside(>=0 -> 1 else 0) -> FC(500->10)
// B = 65536
//
// FC1 on tensor cores: SINGLE fp16 product (error sigma ~1e-4); every output
// with |v| < 6e-4 is recomputed exactly in fp64 (only the SIGN survives the
// Heaviside, so sub-threshold values are the only ones that matter).
// ---------------------------------------------------------------------------

#define B_TOTAL 65536
#define KDIM 2880
#define NOUT 500
#define NPAD 512
#define FIX_CAP (1u*1024u*1024u)
#define T_FIX 6e-4f

__device__ float         g_h2[(size_t)B_TOTAL * KDIM];   // fp32 activations
__device__ __half        g_a0[(size_t)B_TOTAL * KDIM];   // fp16 activations
__device__ __half        g_b0[(size_t)NPAD * KDIM];      // fp16 weights
__device__ unsigned char g_s[(size_t)B_TOTAL * NOUT];    // heaviside bytes
__device__ unsigned int  g_fix[FIX_CAP];                 // fixup worklist
__device__ unsigned int  g_nfix;

__device__ __forceinline__ uint32_t smem_u32(const void* p) {
    uint32_t a;
    asm("{ .reg .u64 t; cvta.to.shared.u64 t, %1; cvt.u32.u64 %0, t; }" : "=r"(a) : "l"(p));
    return a;
}

__device__ __forceinline__ void cp16(uint32_t dst, const void* src) {
    asm volatile("cp.async.cg.shared.global [%0], [%1], 16;" :: "r"(dst), "l"(src));
}

__device__ __forceinline__ void ldx4(uint32_t* r, uint32_t addr) {
    asm volatile("ldmatrix.sync.aligned.m8n8.x4.shared.b16 {%0,%1,%2,%3}, [%4];"
                 : "=r"(r[0]), "=r"(r[1]), "=r"(r[2]), "=r"(r[3]) : "r"(addr));
}

__device__ __forceinline__ void mma16816(float* c, const uint32_t* a,
                                         uint32_t b0, uint32_t b1) {
    asm volatile(
        "mma.sync.aligned.m16n8k16.row.col.f32.f16.f16.f32 "
        "{%0,%1,%2,%3}, {%4,%5,%6,%7}, {%8,%9}, {%0,%1,%2,%3};"
        : "+f"(c[0]), "+f"(c[1]), "+f"(c[2]), "+f"(c[3])
        : "r"(a[0]), "r"(a[1]), "r"(a[2]), "r"(a[3]), "r"(b0), "r"(b1));
}

// ---------------------------------------------------------------------------
// Kernel 0: weight fp16 conversion + counter reset
// ---------------------------------------------------------------------------
__global__ __launch_bounds__(256)
void prep_kernel(const float* __restrict__ W)
{
    const size_t idx = (size_t)blockIdx.x * 256 + threadIdx.x;
    if (idx == 0) g_nfix = 0;
    if (idx >= (size_t)NPAD * KDIM) return;
    const int n = (int)(idx / KDIM);
    const float w = (n < NOUT) ? W[(size_t)n * KDIM + (idx % KDIM)] : 0.f;
    g_b0[idx] = __float2half_rn(w);
}

// ---------------------------------------------------------------------------
// Kernel 1: fused conv1+relu+conv2+relu; writes fp32 h2 + fp16 copy
// ---------------------------------------------------------------------------
__global__ __launch_bounds__(256)
void conv_fused_kernel(const float* __restrict__ x,
                       const float* __restrict__ w1, const float* __restrict__ b1,
                       const float* __restrict__ w2, const float* __restrict__ b2)
{
    __shared__ float sx[768];
    __shared__ float sw1[270];
    __shared__ float sw2[1800];
    __shared__ float sh1[1960];

    const int b = blockIdx.x;
    const int tid = threadIdx.x;

    const float* xb = x + (size_t)b * 768;
    for (int i = tid; i < 768; i += 256)  sx[i]  = xb[i];
    for (int i = tid; i < 270; i += 256)  sw1[i] = w1[i];
    for (int i = tid; i < 1800; i += 256) sw2[i] = w2[i];
    __syncthreads();

    if (tid < 140) {
        const int oc = tid / 14;
        const int oy = tid % 14;
        float acc[14];
        const float bias = b1[oc];
        #pragma unroll
        for (int i = 0; i < 14; i++) acc[i] = bias;

        #pragma unroll
        for (int ic = 0; ic < 3; ic++) {
            const float* xr = sx + ic * 256 + oy * 16;
            const float* w  = sw1 + oc * 27 + ic * 9;
            #pragma unroll
            for (int ky = 0; ky < 3; ky++) {
                const float* row = xr + ky * 16;
                const float wa = w[ky * 3 + 0];
                const float wb = w[ky * 3 + 1];
                const float wc = w[ky * 3 + 2];
                #pragma unroll
                for (int ox = 0; ox < 14; ox++)
                    acc[ox] += wa * row[ox] + wb * row[ox + 1] + wc * row[ox + 2];
            }
        }
        float* out = sh1 + oc * 196 + oy * 14;
        #pragma unroll
        for (int i = 0; i < 14; i++) out[i] = fmaxf(acc[i], 0.f);
    }
    __syncthreads();

    if (tid < 240) {
        const int oc = tid / 12;
        const int oy = tid % 12;
        float acc[12];
        const float bias = b2[oc];
        #pragma unroll
        for (int i = 0; i < 12; i++) acc[i] = bias;

        for (int ic = 0; ic < 10; ic++) {
            const float* hr = sh1 + ic * 196 + oy * 14;
            const float* w  = sw2 + oc * 90 + ic * 9;
            #pragma unroll
            for (int ky = 0; ky < 3; ky++) {
                const float* row = hr + ky * 14;
                const float wa = w[ky * 3 + 0];
                const float wb = w[ky * 3 + 1];
                const float wc = w[ky * 3 + 2];
                #pragma unroll
                for (int ox = 0; ox < 12; ox++)
                    acc[ox] += wa * row[ox] + wb * row[ox + 1] + wc * row[ox + 2];
            }
        }
        float v[12];
        #pragma unroll
        for (int i = 0; i < 12; i++) v[i] = fmaxf(acc[i], 0.f);

        const size_t off = (size_t)b * KDIM + oc * 144 + oy * 12;

        float* outf = g_h2 + off;
        #pragma unroll
        for (int q = 0; q < 3; q++)
            reinterpret_cast<float4*>(outf)[q] =
                make_float4(v[q*4], v[q*4+1], v[q*4+2], v[q*4+3]);

        __half2* p0 = reinterpret_cast<__half2*>(g_a0 + off);
        #pragma unroll
        for (int q = 0; q < 6; q++)
            p0[q] = __floats2half2_rn(v[2*q], v[2*q+1]);
    }
}

// ---------------------------------------------------------------------------
// Kernel 2: FC1 via mma.sync fp16, 128x128 CTA tile, BK=32, 3-stage cp.async.
// smem rows padded to 80B (conflict-free ldmatrix).
// ---------------------------------------------------------------------------
#define BK 32
#define PITCH 80
#define TILE_BYTES (128 * PITCH)      // 10240
#define STAGE_BYTES (2 * TILE_BYTES)  // 20480 : A, B
#define NSTAGE 3
#define FC1_SMEM (NSTAGE * STAGE_BYTES)

__device__ __forceinline__ void load_stage(uint32_t sb,
                                           const __half* ga,
                                           const __half* gb,
                                           int k0, int tid)
{
    const __half* srcs[2] = { ga + k0, gb + k0 };
    #pragma unroll
    for (int t = 0; t < 2; ++t) {
        #pragma unroll
        for (int h = 0; h < 2; ++h) {
            const int idx = h * 256 + tid;        // 0..511
            const int r = idx >> 2, c = idx & 3;
            cp16(sb + t * TILE_BYTES + r * PITCH + c * 16,
                 srcs[t] + (size_t)r * KDIM + c * 8);
        }
    }
}

__global__ __launch_bounds__(256, 2)
void fc1_mma_kernel(const float* __restrict__ bias)
{
    extern __shared__ char sm[];
    const uint32_t smb = smem_u32(sm);
    const int tid  = threadIdx.x;
    const int lane = tid & 31;
    const int wid  = tid >> 5;
    const int n0 = blockIdx.x * 128;
    const int m0 = blockIdx.y * 128;

    const int m_off = (wid & 1) * 64;   // warp covers 64 m
    const int n_off = (wid >> 1) * 32;  // warp covers 32 n

    const __half* ga = g_a0 + (size_t)m0 * KDIM;
    const __half* gb = g_b0 + (size_t)n0 * KDIM;

    float acc[4][4][4];
    #pragma unroll
    for (int i = 0; i < 4; i++)
        #pragma unroll
        for (int j = 0; j < 4; j++)
            #pragma unroll
            for (int q = 0; q < 4; q++) acc[i][j][q] = 0.f;

    load_stage(smb, ga, gb, 0, tid);
    asm volatile("cp.async.commit_group;");
    load_stage(smb + STAGE_BYTES, ga, gb, BK, tid);
    asm volatile("cp.async.commit_group;");

    const uint32_t a_lane = (uint32_t)(lane & 15) * PITCH + (uint32_t)(lane >> 4) * 16;
    const uint32_t b_lane = (uint32_t)(lane & 7) * PITCH + (uint32_t)(lane >> 3) * 16;

    for (int i = 0; i < KDIM / BK; ++i) {
        asm volatile("cp.async.wait_group 1;");
        __syncthreads();
        if (i + 2 < KDIM / BK)
            load_stage(smb + ((i + 2) % NSTAGE) * STAGE_BYTES,
                       ga, gb, (i + 2) * BK, tid);
        asm volatile("cp.async.commit_group;");

        const uint32_t sb = smb + (i % NSTAGE) * STAGE_BYTES;
        const uint32_t Ab = sb;
        const uint32_t Bb = sb + TILE_BYTES;

        uint32_t bf[4][4];
        #pragma unroll
        for (int nt = 0; nt < 4; ++nt)
            ldx4(bf[nt], Bb + (uint32_t)(n_off + nt * 8) * PITCH + b_lane);

        #pragma unroll
        for (int kk = 0; kk < 2; ++kk) {
            uint32_t af[4][4];
            #pragma unroll
            for (int mt = 0; mt < 4; ++mt)
                ldx4(af[mt], Ab + (uint32_t)(m_off + mt * 16) * PITCH + a_lane
                             + (uint32_t)kk * 32);
            #pragma unroll
            for (int mt = 0; mt < 4; ++mt)
                #pragma unroll
                for (int nt = 0; nt < 4; ++nt)
                    mma16816(acc[mt][nt], af[mt], bf[nt][kk*2], bf[nt][kk*2+1]);
        }
    }

    // epilogue: bias + heaviside -> bytes; flag near-zeros for exact recompute
    const int g  = lane >> 2;
    const int t2 = (lane & 3) * 2;
    #pragma unroll
    for (int mt = 0; mt < 4; ++mt) {
        const int mA = m0 + m_off + mt * 16 + g;
        const int mB = mA + 8;
        #pragma unroll
        for (int nt = 0; nt < 4; ++nt) {
            const int n = n0 + n_off + nt * 8 + t2;
            if (n >= NOUT) continue;
            const float bn0 = __ldg(&bias[n]);
            const float bn1 = __ldg(&bias[n + 1]);

            const float vA0 = acc[mt][nt][0] + bn0;
            const float vA1 = acc[mt][nt][1] + bn1;
            const float vB0 = acc[mt][nt][2] + bn0;
            const float vB1 = acc[mt][nt][3] + bn1;

            unsigned short sA = (vA0 >= 0.f ? 1u : 0u) | ((vA1 >= 0.f ? 1u : 0u) << 8);
            unsigned short sB = (vB0 >= 0.f ? 1u : 0u) | ((vB1 >= 0.f ? 1u : 0u) << 8);
            *reinterpret_cast<unsigned short*>(g_s + (size_t)mA * NOUT + n) = sA;
            *reinterpret_cast<unsigned short*>(g_s + (size_t)mB * NOUT + n) = sB;

            if (fabsf(vA0) < T_FIX) {
                unsigned int ix = atomicAdd(&g_nfix, 1u);
                if (ix < FIX_CAP) g_fix[ix] = ((unsigned int)mA << 9) | (unsigned int)n;
            }
            if (fabsf(vA1) < T_FIX) {
                unsigned int ix = atomicAdd(&g_nfix, 1u);
                if (ix < FIX_CAP) g_fix[ix] = ((unsigned int)mA << 9) | (unsigned int)(n+1);
            }
            if (fabsf(vB0) < T_FIX) {
                unsigned int ix = atomicAdd(&g_nfix, 1u);
                if (ix < FIX_CAP) g_fix[ix] = ((unsigned int)mB << 9) | (unsigned int)n;
            }
            if (fabsf(vB1) < T_FIX) {
                unsigned int ix = atomicAdd(&g_nfix, 1u);
                if (ix < FIX_CAP) g_fix[ix] = ((unsigned int)mB << 9) | (unsigned int)(n+1);
            }
        }
    }
}

// ---------------------------------------------------------------------------
// Kernel 3: fp64 recompute of flagged near-zero dots (warp per entry)
// ---------------------------------------------------------------------------
__global__ __launch_bounds__(256)
void fixup_kernel(const float* __restrict__ W, const float* __restrict__ bias)
{
    const int lane = threadIdx.x & 31;
    const int warp = threadIdx.x >> 5;
    unsigned int total = g_nfix;
    if (total > FIX_CAP) total = FIX_CAP;

    for (unsigned int e = blockIdx.x * 8 + warp; e < total; e += gridDim.x * 8) {
        const unsigned int ent = g_fix[e];
        const int m = (int)(ent >> 9);
        const int n = (int)(ent & 511u);
        const float* hr = g_h2 + (size_t)m * KDIM;
        const float* wr = W + (size_t)n * KDIM;
        double acc = 0.0;
        #pragma unroll 5
        for (int k = lane; k < KDIM; k += 32)
            acc += (double)hr[k] * (double)wr[k];
        #pragma unroll
        for (int off = 16; off > 0; off >>= 1)
            acc += __shfl_down_sync(0xffffffffu, acc, off);
        if (lane == 0) {
            const double v = acc + (double)bias[n];
            g_s[(size_t)m * NOUT + n] = (v >= 0.0) ? 1 : 0;
        }
    }
}

// ---------------------------------------------------------------------------
// Kernel 4: FC2 on binary signs, smem-staged (coalesced), quad per sample
// ---------------------------------------------------------------------------
__global__ __launch_bounds__(256)
void fc2_kernel(const float* __restrict__ W2, const float* __restrict__ b2,
                float* __restrict__ out)
{
    __shared__ float sw[5000];                 // [10][500]
    __shared__ unsigned char ss[64 * 500];     // 64 sample rows

    const int tid = threadIdx.x;
    for (int i = tid; i < 5000; i += 256) sw[i] = W2[i];

    const size_t base = (size_t)blockIdx.x * 64;
    const uint4* gsrc = reinterpret_cast<const uint4*>(g_s + base * NOUT);
    uint4* sdst = reinterpret_cast<uint4*>(ss);
    #pragma unroll
    for (int i = 0; i < 8; ++i) {
        const int idx = i * 256 + tid;
        if (idx < 2000) sdst[idx] = gsrc[idx];
    }
    __syncthreads();

    const int s = tid >> 2;       // sample within block
    const int q = tid & 3;        // quad lane
    const unsigned char* srow = ss + s * NOUT + q * 125;
    const int nq = q * 125;

    float acc[10];
    #pragma unroll
    for (int i = 0; i < 10; i++) acc[i] = 0.f;

    for (int j = 0; j < 125; ++j) {
        const float sv = (float)srow[j];
        #pragma unroll
        for (int i = 0; i < 10; i++)
            acc[i] += sv * sw[i * NOUT + nq + j];
    }

    #pragma unroll
    for (int i = 0; i < 10; i++) {
        acc[i] += __shfl_xor_sync(0xffffffffu, acc[i], 1);
        acc[i] += __shfl_xor_sync(0xffffffffu, acc[i], 2);
    }

    if (q == 0) {
        float* o = out + (base + s) * 10;
        #pragma unroll
        for (int i = 0; i < 10; i++) o[i] = acc[i] + b2[i];
    }
}

// ---------------------------------------------------------------------------
extern "C" void kernel_launch(void* const* d_in, const int* in_sizes, int n_in,
                              void* d_out, int out_size)
{
    const float* x    = (const float*)d_in[0];
    const float* w1   = (const float*)d_in[1];
    const float* b1   = (const float*)d_in[2];
    const float* w2   = (const float*)d_in[3];
    const float* b2   = (const float*)d_in[4];
    const float* fcw  = (const float*)d_in[5];
    const float* fcb  = (const float*)d_in[6];
    const float* fc2w = (const float*)d_in[7];
    const float* fc2b = (const float*)d_in[8];

    cudaFuncSetAttribute(fc1_mma_kernel,
                         cudaFuncAttributeMaxDynamicSharedMemorySize, FC1_SMEM);

    prep_kernel<<<(NPAD * KDIM + 255) / 256, 256>>>(fcw);
    conv_fused_kernel<<<B_TOTAL, 256>>>(x, w1, b1, w2, b2);

    dim3 g1(4, 512);   // 4 N-tiles x 512 M-tiles (consecutive CTAs share m0 -> A L2 reuse)
    fc1_mma_kernel<<<g1, 256, FC1_SMEM>>>(fcb);

    fixup_kernel<<<1024, 256>>>(fcw, fcb);
    fc2_kernel<<<B_TOTAL / 64, 256>>>(fc2w, fc2b, (float*)d_out);
}

// round 5
// speedup vs baseline: 1.7092x; 1.0566x over previous
#include <cuda_runtime.h>
#include <cuda_fp16.h>
#include <cstdint>

// ---------------------------------------------------------------------------
// net: conv3x3(3->10)+relu -> conv3x3(10->20)+relu -> FC(2880->500) ->
//      heaviside(>=0 -> 1 else 0) -> FC(500->10)
// B = 65536
//
// FC1 on tensor cores: single fp16 product; |v| < 6e-4 recomputed in fp64
// (only the SIGN survives the Heaviside).
// Conv rewritten: 4 samples/CTA, register-blocked output channels
// (FMA:LDS 5.5:1) to saturate the FMA pipe instead of the smem crossbar.
// ---------------------------------------------------------------------------

#define B_TOTAL 65536
#define KDIM 2880
#define NOUT 500
#define NPAD 512
#define FIX_CAP (1u*1024u*1024u)
#define T_FIX 6e-4f

__device__ float         g_h2[(size_t)B_TOTAL * KDIM];   // fp32 activations
__device__ __half        g_a0[(size_t)B_TOTAL * KDIM];   // fp16 activations
__device__ __half        g_b0[(size_t)NPAD * KDIM];      // fp16 weights
__device__ unsigned char g_s[(size_t)B_TOTAL * NOUT];    // heaviside bytes
__device__ unsigned int  g_fix[FIX_CAP];                 // fixup worklist
__device__ unsigned int  g_nfix;

__device__ __forceinline__ uint32_t smem_u32(const void* p) {
    uint32_t a;
    asm("{ .reg .u64 t; cvta.to.shared.u64 t, %1; cvt.u32.u64 %0, t; }" : "=r"(a) : "l"(p));
    return a;
}

__device__ __forceinline__ void cp16(uint32_t dst, const void* src) {
    asm volatile("cp.async.cg.shared.global [%0], [%1], 16;" :: "r"(dst), "l"(src));
}

__device__ __forceinline__ void ldx4(uint32_t* r, uint32_t addr) {
    asm volatile("ldmatrix.sync.aligned.m8n8.x4.shared.b16 {%0,%1,%2,%3}, [%4];"
                 : "=r"(r[0]), "=r"(r[1]), "=r"(r[2]), "=r"(r[3]) : "r"(addr));
}

__device__ __forceinline__ void mma16816(float* c, const uint32_t* a,
                                         uint32_t b0, uint32_t b1) {
    asm volatile(
        "mma.sync.aligned.m16n8k16.row.col.f32.f16.f16.f32 "
        "{%0,%1,%2,%3}, {%4,%5,%6,%7}, {%8,%9}, {%0,%1,%2,%3};"
        : "+f"(c[0]), "+f"(c[1]), "+f"(c[2]), "+f"(c[3])
        : "r"(a[0]), "r"(a[1]), "r"(a[2]), "r"(a[3]), "r"(b0), "r"(b1));
}

// ---------------------------------------------------------------------------
// Kernel 0: weight fp16 conversion + counter reset
// ---------------------------------------------------------------------------
__global__ __launch_bounds__(256)
void prep_kernel(const float* __restrict__ W)
{
    const size_t idx = (size_t)blockIdx.x * 256 + threadIdx.x;
    if (idx == 0) g_nfix = 0;
    if (idx >= (size_t)NPAD * KDIM) return;
    const int n = (int)(idx / KDIM);
    const float w = (n < NOUT) ? W[(size_t)n * KDIM + (idx % KDIM)] : 0.f;
    g_b0[idx] = __float2half_rn(w);
}

// ---------------------------------------------------------------------------
// Kernel 1: fused conv1+relu+conv2+relu, 4 samples per CTA.
// conv1: 280 tasks (s x 5 ocg x 14 oy), each 2 oc x 14 ox.
// conv2: 240 tasks (s x 5 ocg x 12 oy), each 4 oc x 12 ox.
// smem (dynamic): sw1[270] sw2[1800] sx[4*768] sh1[4*1960] = 51928 B
// ---------------------------------------------------------------------------
#define CONV_SMEM (12982 * 4)

__global__ __launch_bounds__(256, 2)
void conv_fused_kernel(const float* __restrict__ x,
                       const float* __restrict__ w1, const float* __restrict__ b1,
                       const float* __restrict__ w2, const float* __restrict__ b2)
{
    extern __shared__ float sm[];
    float* sw1 = sm;            // 270
    float* sw2 = sm + 270;      // 1800
    float* sx  = sm + 2070;     // 4*768
    float* sh1 = sm + 5142;     // 4*1960

    const int tid = threadIdx.x;
    const size_t b0 = (size_t)blockIdx.x * 4;

    const float* xb = x + b0 * 768;
    #pragma unroll
    for (int i = 0; i < 12; ++i) sx[i * 256 + tid] = xb[i * 256 + tid];
    for (int i = tid; i < 270; i += 256)  sw1[i] = w1[i];
    for (int i = tid; i < 1800; i += 256) sw2[i] = w2[i];
    __syncthreads();

    // ---- conv1 ----
    for (int t = tid; t < 280; t += 256) {
        const int s   = t / 70;
        const int r   = t % 70;
        const int ocg = r / 14;
        const int oy  = r % 14;
        const int oc  = ocg * 2;

        float acc0[14], acc1[14];
        const float bz0 = b1[oc], bz1 = b1[oc + 1];
        #pragma unroll
        for (int i = 0; i < 14; i++) { acc0[i] = bz0; acc1[i] = bz1; }

        #pragma unroll
        for (int ic = 0; ic < 3; ic++) {
            const float* w0 = sw1 + oc * 27 + ic * 9;
            const float* w1p = w0 + 27;
            #pragma unroll
            for (int ky = 0; ky < 3; ky++) {
                const float* row = sx + s * 768 + ic * 256 + (oy + ky) * 16;
                const float wa0 = w0[ky*3+0], wb0 = w0[ky*3+1], wc0 = w0[ky*3+2];
                const float wa1 = w1p[ky*3+0], wb1 = w1p[ky*3+1], wc1 = w1p[ky*3+2];
                #pragma unroll
                for (int ox = 0; ox < 14; ox++) {
                    const float x0 = row[ox], x1 = row[ox+1], x2 = row[ox+2];
                    acc0[ox] += wa0 * x0 + wb0 * x1 + wc0 * x2;
                    acc1[ox] += wa1 * x0 + wb1 * x1 + wc1 * x2;
                }
            }
        }
        float* o0 = sh1 + s * 1960 + oc * 196 + oy * 14;
        float* o1 = o0 + 196;
        #pragma unroll
        for (int i = 0; i < 14; i++) {
            o0[i] = fmaxf(acc0[i], 0.f);
            o1[i] = fmaxf(acc1[i], 0.f);
        }
    }
    __syncthreads();

    // ---- conv2 ----
    if (tid < 240) {
        const int s   = tid / 60;
        const int r   = tid % 60;
        const int ocg = r / 12;
        const int oy  = r % 12;
        const int oc  = ocg * 4;

        float acc[4][12];
        #pragma unroll
        for (int j = 0; j < 4; j++) {
            const float bz = b2[oc + j];
            #pragma unroll
            for (int i = 0; i < 12; i++) acc[j][i] = bz;
        }

        #pragma unroll 2
        for (int ic = 0; ic < 10; ic++) {
            float wv[4][9];
            #pragma unroll
            for (int j = 0; j < 4; j++) {
                const float* w = sw2 + (oc + j) * 90 + ic * 9;
                #pragma unroll
                for (int q = 0; q < 9; q++) wv[j][q] = w[q];
            }
            const float* rbase = sh1 + s * 1960 + ic * 196 + oy * 14;
            #pragma unroll
            for (int ky = 0; ky < 3; ky++) {
                const float* row = rbase + ky * 14;
                #pragma unroll
                for (int ox = 0; ox < 12; ox++) {
                    const float x0 = row[ox], x1 = row[ox+1], x2 = row[ox+2];
                    #pragma unroll
                    for (int j = 0; j < 4; j++)
                        acc[j][ox] += wv[j][ky*3+0] * x0 + wv[j][ky*3+1] * x1
                                    + wv[j][ky*3+2] * x2;
                }
            }
        }

        const size_t sbase = (b0 + s) * KDIM + oc * 144 + oy * 12;
        #pragma unroll
        for (int j = 0; j < 4; j++) {
            float v[12];
            #pragma unroll
            for (int i = 0; i < 12; i++) v[i] = fmaxf(acc[j][i], 0.f);

            float* outf = g_h2 + sbase + j * 144;
            #pragma unroll
            for (int q = 0; q < 3; q++)
                reinterpret_cast<float4*>(outf)[q] =
                    make_float4(v[q*4], v[q*4+1], v[q*4+2], v[q*4+3]);

            __half2* p0 = reinterpret_cast<__half2*>(g_a0 + sbase + j * 144);
            #pragma unroll
            for (int q = 0; q < 6; q++)
                p0[q] = __floats2half2_rn(v[2*q], v[2*q+1]);
        }
    }
}

// ---------------------------------------------------------------------------
// Kernel 2: FC1 via mma.sync fp16, 128x128 CTA tile, BK=32, 3-stage cp.async.
// ---------------------------------------------------------------------------
#define BK 32
#define PITCH 80
#define TILE_BYTES (128 * PITCH)      // 10240
#define STAGE_BYTES (2 * TILE_BYTES)  // 20480 : A, B
#define NSTAGE 3
#define FC1_SMEM (NSTAGE * STAGE_BYTES)

__device__ __forceinline__ void load_stage(uint32_t sb,
                                           const __half* ga,
                                           const __half* gb,
                                           int k0, int tid)
{
    const __half* srcs[2] = { ga + k0, gb + k0 };
    #pragma unroll
    for (int t = 0; t < 2; ++t) {
        #pragma unroll
        for (int h = 0; h < 2; ++h) {
            const int idx = h * 256 + tid;        // 0..511
            const int r = idx >> 2, c = idx & 3;
            cp16(sb + t * TILE_BYTES + r * PITCH + c * 16,
                 srcs[t] + (size_t)r * KDIM + c * 8);
        }
    }
}

__global__ __launch_bounds__(256, 2)
void fc1_mma_kernel(const float* __restrict__ bias)
{
    extern __shared__ char smc[];
    const uint32_t smb = smem_u32(smc);
    const int tid  = threadIdx.x;
    const int lane = tid & 31;
    const int wid  = tid >> 5;
    const int n0 = blockIdx.x * 128;
    const int m0 = blockIdx.y * 128;

    const int m_off = (wid & 1) * 64;
    const int n_off = (wid >> 1) * 32;

    const __half* ga = g_a0 + (size_t)m0 * KDIM;
    const __half* gb = g_b0 + (size_t)n0 * KDIM;

    float acc[4][4][4];
    #pragma unroll
    for (int i = 0; i < 4; i++)
        #pragma unroll
        for (int j = 0; j < 4; j++)
            #pragma unroll
            for (int q = 0; q < 4; q++) acc[i][j][q] = 0.f;

    load_stage(smb, ga, gb, 0, tid);
    asm volatile("cp.async.commit_group;");
    load_stage(smb + STAGE_BYTES, ga, gb, BK, tid);
    asm volatile("cp.async.commit_group;");

    const uint32_t a_lane = (uint32_t)(lane & 15) * PITCH + (uint32_t)(lane >> 4) * 16;
    const uint32_t b_lane = (uint32_t)(lane & 7) * PITCH + (uint32_t)(lane >> 3) * 16;

    for (int i = 0; i < KDIM / BK; ++i) {
        asm volatile("cp.async.wait_group 1;");
        __syncthreads();
        if (i + 2 < KDIM / BK)
            load_stage(smb + ((i + 2) % NSTAGE) * STAGE_BYTES,
                       ga, gb, (i + 2) * BK, tid);
        asm volatile("cp.async.commit_group;");

        const uint32_t sb = smb + (i % NSTAGE) * STAGE_BYTES;
        const uint32_t Ab = sb;
        const uint32_t Bb = sb + TILE_BYTES;

        uint32_t bf[4][4];
        #pragma unroll
        for (int nt = 0; nt < 4; ++nt)
            ldx4(bf[nt], Bb + (uint32_t)(n_off + nt * 8) * PITCH + b_lane);

        #pragma unroll
        for (int kk = 0; kk < 2; ++kk) {
            uint32_t af[4][4];
            #pragma unroll
            for (int mt = 0; mt < 4; ++mt)
                ldx4(af[mt], Ab + (uint32_t)(m_off + mt * 16) * PITCH + a_lane
                             + (uint32_t)kk * 32);
            #pragma unroll
            for (int mt = 0; mt < 4; ++mt)
                #pragma unroll
                for (int nt = 0; nt < 4; ++nt)
                    mma16816(acc[mt][nt], af[mt], bf[nt][kk*2], bf[nt][kk*2+1]);
        }
    }

    const int g  = lane >> 2;
    const int t2 = (lane & 3) * 2;
    #pragma unroll
    for (int mt = 0; mt < 4; ++mt) {
        const int mA = m0 + m_off + mt * 16 + g;
        const int mB = mA + 8;
        #pragma unroll
        for (int nt = 0; nt < 4; ++nt) {
            const int n = n0 + n_off + nt * 8 + t2;
            if (n >= NOUT) continue;
            const float bn0 = __ldg(&bias[n]);
            const float bn1 = __ldg(&bias[n + 1]);

            const float vA0 = acc[mt][nt][0] + bn0;
            const float vA1 = acc[mt][nt][1] + bn1;
            const float vB0 = acc[mt][nt][2] + bn0;
            const float vB1 = acc[mt][nt][3] + bn1;

            unsigned short sA = (vA0 >= 0.f ? 1u : 0u) | ((vA1 >= 0.f ? 1u : 0u) << 8);
            unsigned short sB = (vB0 >= 0.f ? 1u : 0u) | ((vB1 >= 0.f ? 1u : 0u) << 8);
            *reinterpret_cast<unsigned short*>(g_s + (size_t)mA * NOUT + n) = sA;
            *reinterpret_cast<unsigned short*>(g_s + (size_t)mB * NOUT + n) = sB;

            if (fabsf(vA0) < T_FIX) {
                unsigned int ix = atomicAdd(&g_nfix, 1u);
                if (ix < FIX_CAP) g_fix[ix] = ((unsigned int)mA << 9) | (unsigned int)n;
            }
            if (fabsf(vA1) < T_FIX) {
                unsigned int ix = atomicAdd(&g_nfix, 1u);
                if (ix < FIX_CAP) g_fix[ix] = ((unsigned int)mA << 9) | (unsigned int)(n+1);
            }
            if (fabsf(vB0) < T_FIX) {
                unsigned int ix = atomicAdd(&g_nfix, 1u);
                if (ix < FIX_CAP) g_fix[ix] = ((unsigned int)mB << 9) | (unsigned int)n;
            }
            if (fabsf(vB1) < T_FIX) {
                unsigned int ix = atomicAdd(&g_nfix, 1u);
                if (ix < FIX_CAP) g_fix[ix] = ((unsigned int)mB << 9) | (unsigned int)(n+1);
            }
        }
    }
}

// ---------------------------------------------------------------------------
// Kernel 3: fp64 recompute of flagged near-zero dots (warp per entry)
// ---------------------------------------------------------------------------
__global__ __launch_bounds__(256)
void fixup_kernel(const float* __restrict__ W, const float* __restrict__ bias)
{
    const int lane = threadIdx.x & 31;
    const int warp = threadIdx.x >> 5;
    unsigned int total = g_nfix;
    if (total > FIX_CAP) total = FIX_CAP;

    for (unsigned int e = blockIdx.x * 8 + warp; e < total; e += gridDim.x * 8) {
        const unsigned int ent = g_fix[e];
        const int m = (int)(ent >> 9);
        const int n = (int)(ent & 511u);
        const float* hr = g_h2 + (size_t)m * KDIM;
        const float* wr = W + (size_t)n * KDIM;
        double acc = 0.0;
        #pragma unroll 5
        for (int k = lane; k < KDIM; k += 32)
            acc += (double)hr[k] * (double)wr[k];
        #pragma unroll
        for (int off = 16; off > 0; off >>= 1)
            acc += __shfl_down_sync(0xffffffffu, acc, off);
        if (lane == 0) {
            const double v = acc + (double)bias[n];
            g_s[(size_t)m * NOUT + n] = (v >= 0.0) ? 1 : 0;
        }
    }
}

// ---------------------------------------------------------------------------
// Kernel 4: FC2 on binary signs, smem-staged, quad per sample
// ---------------------------------------------------------------------------
__global__ __launch_bounds__(256)
void fc2_kernel(const float* __restrict__ W2, const float* __restrict__ b2,
                float* __restrict__ out)
{
    __shared__ float sw[5000];                 // [10][500]
    __shared__ unsigned char ss[64 * 500];     // 64 sample rows

    const int tid = threadIdx.x;
    for (int i = tid; i < 5000; i += 256) sw[i] = W2[i];

    const size_t base = (size_t)blockIdx.x * 64;
    const uint4* gsrc = reinterpret_cast<const uint4*>(g_s + base * NOUT);
    uint4* sdst = reinterpret_cast<uint4*>(ss);
    #pragma unroll
    for (int i = 0; i < 8; ++i) {
        const int idx = i * 256 + tid;
        if (idx < 2000) sdst[idx] = gsrc[idx];
    }
    __syncthreads();

    const int s = tid >> 2;
    const int q = tid & 3;
    const unsigned char* srow = ss + s * NOUT + q * 125;
    const int nq = q * 125;

    float acc[10];
    #pragma unroll
    for (int i = 0; i < 10; i++) acc[i] = 0.f;

    for (int j = 0; j < 125; ++j) {
        const float sv = (float)srow[j];
        #pragma unroll
        for (int i = 0; i < 10; i++)
            acc[i] += sv * sw[i * NOUT + nq + j];
    }

    #pragma unroll
    for (int i = 0; i < 10; i++) {
        acc[i] += __shfl_xor_sync(0xffffffffu, acc[i], 1);
        acc[i] += __shfl_xor_sync(0xffffffffu, acc[i], 2);
    }

    if (q == 0) {
        float* o = out + (base + s) * 10;
        #pragma unroll
        for (int i = 0; i < 10; i++) o[i] = acc[i] + b2[i];
    }
}

// ---------------------------------------------------------------------------
extern "C" void kernel_launch(void* const* d_in, const int* in_sizes, int n_in,
                              void* d_out, int out_size)
{
    const float* x    = (const float*)d_in[0];
    const float* w1   = (const float*)d_in[1];
    const float* b1   = (const float*)d_in[2];
    const float* w2   = (const float*)d_in[3];
    const float* b2   = (const float*)d_in[4];
    const float* fcw  = (const float*)d_in[5];
    const float* fcb  = (const float*)d_in[6];
    const float* fc2w = (const float*)d_in[7];
    const float* fc2b = (const float*)d_in[8];

    cudaFuncSetAttribute(conv_fused_kernel,
                         cudaFuncAttributeMaxDynamicSharedMemorySize, CONV_SMEM);
    cudaFuncSetAttribute(fc1_mma_kernel,
                         cudaFuncAttributeMaxDynamicSharedMemorySize, FC1_SMEM);

    prep_kernel<<<(NPAD * KDIM + 255) / 256, 256>>>(fcw);
    conv_fused_kernel<<<B_TOTAL / 4, 256, CONV_SMEM>>>(x, w1, b1, w2, b2);

    dim3 g1(4, 512);
    fc1_mma_kernel<<<g1, 256, FC1_SMEM>>>(fcb);

    fixup_kernel<<<1024, 256>>>(fcw, fcb);
    fc2_kernel<<<B_TOTAL / 64, 256>>>(fc2w, fc2b, (float*)d_out);
}